// round 3
// baseline (speedup 1.0000x reference)
#include <cuda_runtime.h>
#include <cuda_bf16.h>
#include <cstdint>

// Loss_Labels: -mean over B of ( label==1 ? log_softmax(s,a)[0]
//                              : label==2 ? log_softmax(s,a)[1] : 0 )
//
// Labels are int32 on device (JAX x64 disabled). 12 B/element streamed,
// B = 8.4M -> ~100 MB. HBM-bound. Single fused kernel: last block to finish
// performs the (deterministic, fixed-order) final reduction -> no 2nd launch.

#define NB 2048
#define NT 256

__device__ float g_partials[NB];
__device__ unsigned int g_done_count;   // zero-initialized; reset by last block

__device__ __forceinline__ float err_term(float s, float a, int lab) {
    // d = a - s; lse - s = max(d,0) + log1p(exp(-|d|))
    float d   = a - s;
    float lp0 = -(fmaxf(d, 0.0f) + log1pf(expf(-fabsf(d))));  // log p(syn)
    float lp1 = d + lp0;                                       // log p(ant)
    return (lab == 1) ? lp0 : ((lab == 2) ? lp1 : 0.0f);
}

__global__ void __launch_bounds__(NT)
loss_fused_kernel(const float4* __restrict__ s4,
                  const float4* __restrict__ a4,
                  const int4*   __restrict__ l4,
                  const float*  __restrict__ s,
                  const float*  __restrict__ a,
                  const int*    __restrict__ lab,
                  float* __restrict__ out,
                  int n, int nvec)
{
    float acc = 0.0f;
    const int stride = gridDim.x * blockDim.x;
    int i = blockIdx.x * blockDim.x + threadIdx.x;

    // 2-way unrolled grid-stride loop: 6 independent 128-bit loads in flight.
    for (; i + stride < nvec; i += 2 * stride) {
        float4 sA = s4[i];           float4 sB = s4[i + stride];
        float4 aA = a4[i];           float4 aB = a4[i + stride];
        int4   lA = l4[i];           int4   lB = l4[i + stride];
        acc += err_term(sA.x, aA.x, lA.x);
        acc += err_term(sA.y, aA.y, lA.y);
        acc += err_term(sA.z, aA.z, lA.z);
        acc += err_term(sA.w, aA.w, lA.w);
        acc += err_term(sB.x, aB.x, lB.x);
        acc += err_term(sB.y, aB.y, lB.y);
        acc += err_term(sB.z, aB.z, lB.z);
        acc += err_term(sB.w, aB.w, lB.w);
    }
    if (i < nvec) {
        float4 sA = s4[i];
        float4 aA = a4[i];
        int4   lA = l4[i];
        acc += err_term(sA.x, aA.x, lA.x);
        acc += err_term(sA.y, aA.y, lA.y);
        acc += err_term(sA.z, aA.z, lA.z);
        acc += err_term(sA.w, aA.w, lA.w);
    }

    // scalar tail (n % 4 != 0); n = 8388608 is divisible, kept for safety
    if (blockIdx.x == 0) {
        for (int t = nvec * 4 + threadIdx.x; t < n; t += NT)
            acc += err_term(s[t], a[t], lab[t]);
    }

    // deterministic block tree reduction
    __shared__ float sm[NT];
    sm[threadIdx.x] = acc;
    __syncthreads();
#pragma unroll
    for (int off = NT / 2; off > 0; off >>= 1) {
        if (threadIdx.x < off) sm[threadIdx.x] += sm[threadIdx.x + off];
        __syncthreads();
    }

    __shared__ bool s_last;
    if (threadIdx.x == 0) {
        g_partials[blockIdx.x] = sm[0];
        __threadfence();
        unsigned int prev = atomicAdd(&g_done_count, 1u);
        s_last = (prev == (unsigned int)(gridDim.x - 1));
    }
    __syncthreads();

    if (s_last) {
        // last block: fixed-order sum of all partials -> deterministic
        __threadfence();  // make all partials visible
        float facc = 0.0f;
        const float4* p4 = (const float4*)g_partials;
#pragma unroll
        for (int k = threadIdx.x; k < NB / 4; k += NT) {
            float4 p = p4[k];
            facc += p.x + p.y + p.z + p.w;
        }
        sm[threadIdx.x] = facc;
        __syncthreads();
#pragma unroll
        for (int off = NT / 2; off > 0; off >>= 1) {
            if (threadIdx.x < off) sm[threadIdx.x] += sm[threadIdx.x + off];
            __syncthreads();
        }
        if (threadIdx.x == 0) {
            out[0] = -sm[0] / (float)n;
            g_done_count = 0;   // reset for next graph replay
        }
    }
}

extern "C" void kernel_launch(void* const* d_in, const int* in_sizes, int n_in,
                              void* d_out, int out_size)
{
    const float* s   = (const float*)d_in[0];  // synonymy_score [B]
    const float* a   = (const float*)d_in[1];  // antonymy_score [B]
    const int*   lab = (const int*)d_in[2];    // labels [B] (int32 on device)
    float*       out = (float*)d_out;

    const int n    = in_sizes[0];
    const int nvec = n / 4;

    loss_fused_kernel<<<NB, NT>>>((const float4*)s, (const float4*)a,
                                  (const int4*)lab, s, a, lab, out, n, nvec);
}

// round 4
// speedup vs baseline: 1.0111x; 1.0111x over previous
#include <cuda_runtime.h>
#include <cuda_bf16.h>
#include <cstdint>

// Loss_Labels: -mean over B of ( label==1 ? log_softmax(s,a)[0]
//                              : label==2 ? log_softmax(s,a)[1] : 0 )
//
// Labels are int32 on device (JAX x64 disabled). 12 B/element streamed,
// B = 8.4M -> ~100 MB. HBM-bound.
// R4: simple 1x grid-stride body (low regs, full occupancy) + in-kernel
// last-block finalize (no 2nd launch). launch_bounds forces 8 blocks/SM.

#define NB 2048
#define NT 256

__device__ float g_partials[NB];
__device__ unsigned int g_done_count;   // zero-init; reset by last block

__device__ __forceinline__ float err_term(float s, float a, int lab) {
    // d = a - s; lse - s = max(d,0) + log1p(exp(-|d|))
    float d   = a - s;
    float lp0 = -(fmaxf(d, 0.0f) + log1pf(expf(-fabsf(d))));  // log p(syn)
    float lp1 = d + lp0;                                       // log p(ant)
    return (lab == 1) ? lp0 : ((lab == 2) ? lp1 : 0.0f);
}

__global__ void __launch_bounds__(NT, 8)
loss_fused_kernel(const float4* __restrict__ s4,
                  const float4* __restrict__ a4,
                  const int4*   __restrict__ l4,
                  float* __restrict__ out,
                  int n, int nvec)
{
    float acc = 0.0f;
    const int stride = gridDim.x * blockDim.x;
    for (int i = blockIdx.x * blockDim.x + threadIdx.x; i < nvec; i += stride) {
        float4 s = s4[i];
        float4 a = a4[i];
        int4   l = l4[i];
        acc += err_term(s.x, a.x, l.x);
        acc += err_term(s.y, a.y, l.y);
        acc += err_term(s.z, a.z, l.z);
        acc += err_term(s.w, a.w, l.w);
    }

    // scalar tail (n % 4 != 0); n = 8388608 divisible, kept for safety
    if (blockIdx.x == 0) {
        const float* s = (const float*)s4;
        const float* a = (const float*)a4;
        const int*   l = (const int*)l4;
        for (int t = nvec * 4 + threadIdx.x; t < n; t += NT)
            acc += err_term(s[t], a[t], l[t]);
    }

    // deterministic block tree reduction
    __shared__ float sm[NT];
    sm[threadIdx.x] = acc;
    __syncthreads();
#pragma unroll
    for (int off = NT / 2; off > 0; off >>= 1) {
        if (threadIdx.x < off) sm[threadIdx.x] += sm[threadIdx.x + off];
        __syncthreads();
    }

    __shared__ bool s_last;
    if (threadIdx.x == 0) {
        g_partials[blockIdx.x] = sm[0];
        __threadfence();
        unsigned int prev = atomicAdd(&g_done_count, 1u);
        s_last = (prev == (unsigned int)(gridDim.x - 1));
    }
    __syncthreads();

    if (s_last) {
        __threadfence();  // all partials visible
        float facc = 0.0f;
        const float4* p4 = (const float4*)g_partials;
#pragma unroll
        for (int k = threadIdx.x; k < NB / 4; k += NT) {
            float4 p = p4[k];
            facc += p.x + p.y + p.z + p.w;
        }
        sm[threadIdx.x] = facc;
        __syncthreads();
#pragma unroll
        for (int off = NT / 2; off > 0; off >>= 1) {
            if (threadIdx.x < off) sm[threadIdx.x] += sm[threadIdx.x + off];
            __syncthreads();
        }
        if (threadIdx.x == 0) {
            out[0] = -sm[0] / (float)n;
            g_done_count = 0;   // reset for next graph replay
        }
    }
}

extern "C" void kernel_launch(void* const* d_in, const int* in_sizes, int n_in,
                              void* d_out, int out_size)
{
    const float* s   = (const float*)d_in[0];  // synonymy_score [B]
    const float* a   = (const float*)d_in[1];  // antonymy_score [B]
    const int*   lab = (const int*)d_in[2];    // labels [B] (int32 on device)
    float*       out = (float*)d_out;

    const int n    = in_sizes[0];
    const int nvec = n / 4;

    loss_fused_kernel<<<NB, NT>>>((const float4*)s, (const float4*)a,
                                  (const int4*)lab, out, n, nvec);
}

// round 5
// speedup vs baseline: 1.2194x; 1.2060x over previous
#include <cuda_runtime.h>
#include <cuda_bf16.h>
#include <cstdint>

// Loss_Labels: -mean over B of ( label==1 ? log_softmax(s,a)[0]
//                              : label==2 ? log_softmax(s,a)[1] : 0 )
//
// Labels are int32 on device. 12 B/element streamed, ~100 MB total. HBM-bound
// target. R5: (a) fast-math __logf/__expf replaces libm log1pf (was issue-
// bound at 70%), (b) grid = 148 SMs * 8 blocks = 1184 -> exactly one wave,
// no wave-quantization tail. In-kernel last-block finalize (single launch).

#define NB 1184          // 148 SMs * 8 blocks/SM: one full wave
#define NT 256

__device__ float g_partials[NB];
__device__ unsigned int g_done_count;   // zero-init; reset by last block

__device__ __forceinline__ float err_term(float s, float a, int lab) {
    // d = a - s; lse - s = max(d,0) + log(1 + exp(-|d|))  (arg in (1,2])
    float d   = a - s;
    float t   = fmaxf(d, 0.0f) + __logf(1.0f + __expf(-fabsf(d)));
    // lp0 = -t ; lp1 = d - t
    return (lab == 1) ? -t : ((lab == 2) ? (d - t) : 0.0f);
}

__global__ void __launch_bounds__(NT, 8)
loss_fused_kernel(const float4* __restrict__ s4,
                  const float4* __restrict__ a4,
                  const int4*   __restrict__ l4,
                  float* __restrict__ out,
                  int n, int nvec)
{
    float acc = 0.0f;
    const int stride = gridDim.x * blockDim.x;
    for (int i = blockIdx.x * blockDim.x + threadIdx.x; i < nvec; i += stride) {
        float4 s = s4[i];
        float4 a = a4[i];
        int4   l = l4[i];
        acc += err_term(s.x, a.x, l.x);
        acc += err_term(s.y, a.y, l.y);
        acc += err_term(s.z, a.z, l.z);
        acc += err_term(s.w, a.w, l.w);
    }

    // scalar tail (n % 4 != 0); n = 8388608 divisible, kept for safety
    if (blockIdx.x == 0) {
        const float* s = (const float*)s4;
        const float* a = (const float*)a4;
        const int*   l = (const int*)l4;
        for (int t = nvec * 4 + threadIdx.x; t < n; t += NT)
            acc += err_term(s[t], a[t], l[t]);
    }

    // deterministic block tree reduction
    __shared__ float sm[NT];
    sm[threadIdx.x] = acc;
    __syncthreads();
#pragma unroll
    for (int off = NT / 2; off > 0; off >>= 1) {
        if (threadIdx.x < off) sm[threadIdx.x] += sm[threadIdx.x + off];
        __syncthreads();
    }

    __shared__ bool s_last;
    if (threadIdx.x == 0) {
        g_partials[blockIdx.x] = sm[0];
        __threadfence();
        unsigned int prev = atomicAdd(&g_done_count, 1u);
        s_last = (prev == (unsigned int)(gridDim.x - 1));
    }
    __syncthreads();

    if (s_last) {
        __threadfence();  // all partials visible
        float facc = 0.0f;
        for (int k = threadIdx.x; k < NB; k += NT)
            facc += g_partials[k];
        sm[threadIdx.x] = facc;
        __syncthreads();
#pragma unroll
        for (int off = NT / 2; off > 0; off >>= 1) {
            if (threadIdx.x < off) sm[threadIdx.x] += sm[threadIdx.x + off];
            __syncthreads();
        }
        if (threadIdx.x == 0) {
            out[0] = -sm[0] / (float)n;
            g_done_count = 0;   // reset for next graph replay
        }
    }
}

extern "C" void kernel_launch(void* const* d_in, const int* in_sizes, int n_in,
                              void* d_out, int out_size)
{
    const float* s   = (const float*)d_in[0];  // synonymy_score [B]
    const float* a   = (const float*)d_in[1];  // antonymy_score [B]
    const int*   lab = (const int*)d_in[2];    // labels [B] (int32 on device)
    float*       out = (float*)d_out;

    const int n    = in_sizes[0];
    const int nvec = n / 4;

    loss_fused_kernel<<<NB, NT>>>((const float4*)s, (const float4*)a,
                                  (const int4*)lab, out, n, nvec);
}

// round 6
// speedup vs baseline: 1.2297x; 1.0084x over previous
#include <cuda_runtime.h>
#include <cuda_bf16.h>
#include <cstdint>

// Loss_Labels: -mean over B of ( label==1 ? log_softmax(s,a)[0]
//                              : label==2 ? log_softmax(s,a)[1] : 0 )
//
// Labels int32 on device. 12 B/element, ~100 MB streamed. R6: each thread
// processes a contiguous PAIR of float4/int4 vectors -> 6 independent 128-bit
// loads front-batched per iteration (2x MLP vs R5), launch_bounds(256,7)
// (reg cap 36, no spill), grid = 148*7 = one full wave. Fast-math softplus.
// In-kernel last-block finalize (single launch, deterministic).

#define NSM 148
#define OCC 7
#define NB (NSM * OCC)   // 1036 blocks: one full wave at 7 blocks/SM
#define NT 256

__device__ float g_partials[NB];
__device__ unsigned int g_done_count;   // zero-init; reset by last block

__device__ __forceinline__ float err_term(float s, float a, int lab) {
    // d = a - s; lse - s = max(d,0) + log(1 + exp(-|d|))  (arg in (1,2])
    float d = a - s;
    float t = fmaxf(d, 0.0f) + __logf(1.0f + __expf(-fabsf(d)));
    return (lab == 1) ? -t : ((lab == 2) ? (d - t) : 0.0f);
}

__global__ void __launch_bounds__(NT, OCC)
loss_fused_kernel(const float4* __restrict__ s4,
                  const float4* __restrict__ a4,
                  const int4*   __restrict__ l4,
                  float* __restrict__ out,
                  int n, int nvec)
{
    const int npair  = nvec / 2;               // pairs of float4
    const int stride = gridDim.x * blockDim.x;

    float acc = 0.0f;
    for (int i = blockIdx.x * blockDim.x + threadIdx.x; i < npair; i += stride) {
        // 6 independent 128-bit loads, front-batched (contiguous 32B/stream/thread)
        float4 s0 = s4[2 * i];
        float4 s1 = s4[2 * i + 1];
        float4 a0 = a4[2 * i];
        float4 a1 = a4[2 * i + 1];
        int4   l0 = l4[2 * i];
        int4   l1 = l4[2 * i + 1];

        acc += err_term(s0.x, a0.x, l0.x);
        acc += err_term(s0.y, a0.y, l0.y);
        acc += err_term(s0.z, a0.z, l0.z);
        acc += err_term(s0.w, a0.w, l0.w);
        acc += err_term(s1.x, a1.x, l1.x);
        acc += err_term(s1.y, a1.y, l1.y);
        acc += err_term(s1.z, a1.z, l1.z);
        acc += err_term(s1.w, a1.w, l1.w);
    }

    // scalar tail: elements [npair*8, n) (n = 8388608 -> empty; kept for safety)
    if (blockIdx.x == 0) {
        const float* s = (const float*)s4;
        const float* a = (const float*)a4;
        const int*   l = (const int*)l4;
        for (int t = npair * 8 + threadIdx.x; t < n; t += NT)
            acc += err_term(s[t], a[t], l[t]);
    }

    // deterministic block tree reduction
    __shared__ float sm[NT];
    sm[threadIdx.x] = acc;
    __syncthreads();
#pragma unroll
    for (int off = NT / 2; off > 0; off >>= 1) {
        if (threadIdx.x < off) sm[threadIdx.x] += sm[threadIdx.x + off];
        __syncthreads();
    }

    __shared__ bool s_last;
    if (threadIdx.x == 0) {
        g_partials[blockIdx.x] = sm[0];
        __threadfence();
        unsigned int prev = atomicAdd(&g_done_count, 1u);
        s_last = (prev == (unsigned int)(gridDim.x - 1));
    }
    __syncthreads();

    if (s_last) {
        __threadfence();  // all partials visible
        float facc = 0.0f;
        for (int k = threadIdx.x; k < NB; k += NT)
            facc += g_partials[k];
        sm[threadIdx.x] = facc;
        __syncthreads();
#pragma unroll
        for (int off = NT / 2; off > 0; off >>= 1) {
            if (threadIdx.x < off) sm[threadIdx.x] += sm[threadIdx.x + off];
            __syncthreads();
        }
        if (threadIdx.x == 0) {
            out[0] = -sm[0] / (float)n;
            g_done_count = 0;   // reset for next graph replay
        }
    }
}

extern "C" void kernel_launch(void* const* d_in, const int* in_sizes, int n_in,
                              void* d_out, int out_size)
{
    const float* s   = (const float*)d_in[0];  // synonymy_score [B]
    const float* a   = (const float*)d_in[1];  // antonymy_score [B]
    const int*   lab = (const int*)d_in[2];    // labels [B] (int32 on device)
    float*       out = (float*)d_out;

    const int n    = in_sizes[0];
    const int nvec = n / 4;

    loss_fused_kernel<<<NB, NT>>>((const float4*)s, (const float4*)a,
                                  (const int4*)lab, out, n, nvec);
}